// round 16
// baseline (speedup 1.0000x reference)
#include <cuda_runtime.h>
#include <stdint.h>

// MultiLevelHybridHashEncoding — instant-NGP hash-grid encoding.
// R15 -> R16: ptxas packed R15 into 32 regs, so feed is smem-bound only.
// One knob: TPB 832 -> 896 (56 warps/SM, 36-reg budget). First clean test
// of 56 warps with the full winning structure: smem levels 0..1 (96.8KB/CTA,
// 2 CTAs/SM), persistent grid, lane-distributed x-load + shfl broadcast,
// pair-coalesced gathers (lane parity = x-corner), __ldcg for l>=2,
// shfl pair-reduce, __stcs coalesced 128B warp stores.

#define NLEVELS 16
#define TPB 896

#define L0_N 4096    // 16^3
#define L1_N 8000    // 20^3
#define SMEM_BYTES ((L0_N + L1_N) * 8)   // 96768 B per CTA

#define P1 2654435761u
#define P2 805459861u
#define HMASK 0x7FFFFu
#define FULL 0xffffffffu

struct Params {
    const float2* tab[NLEVELS];
};

__device__ __constant__ int c_res[NLEVELS] = {
    16, 20, 25, 32, 40, 50, 64, 80, 101, 128, 161, 203, 256, 322, 406, 512
};

extern __shared__ float2 s_tab[];

__global__ void __launch_bounds__(TPB, 2)
hashenc_kernel(const float* __restrict__ x, Params p,
               float2* __restrict__ out, int B)
{
    // ---- cooperative smem fill: levels 0..1, coalesced ----
    {
        const float2* __restrict__ t0 = p.tab[0];
        const float2* __restrict__ t1 = p.tab[1];
        for (int i = threadIdx.x; i < L0_N; i += TPB) s_tab[i] = __ldg(t0 + i);
        for (int i = threadIdx.x; i < L1_N; i += TPB) s_tab[L0_N + i] = __ldg(t1 + i);
    }
    __syncthreads();

    // Thread = (point, level, x-half). 32 consecutive threads = 1 point.
    const int   lane     = threadIdx.x & 31;
    const int   ox       = threadIdx.x & 1;        // x-corner this lane owns
    const int   l        = (threadIdx.x >> 1) & 15;
    const int   res      = c_res[l];
    const int   res2     = res * res;
    const float sc       = 0.5f * (float)res;
    const bool  in_smem  = (l < 2);
    const bool  use_hash = (l >= 8);
    const float2* __restrict__ gtab = p.tab[l];
    const float2* __restrict__ stab = s_tab + (l == 0 ? 0 : L0_N);

    const int total  = B * NLEVELS * 2;             // (point, level, half) items
    const int stride = gridDim.x * TPB;
    int tid = blockIdx.x * TPB + threadIdx.x;
    if (tid >= total) return;

    // Prologue: lanes 0..2 fetch the 12B point; broadcast via shfl.
    float xv = 0.0f;
    {
        const int b = tid >> 5;
        if (lane < 3) xv = __ldcg(x + 3 * b + lane);
    }
    float px = __shfl_sync(FULL, xv, 0);
    float py = __shfl_sync(FULL, xv, 1);
    float pz = __shfl_sync(FULL, xv, 2);

    while (true) {
        // ---- prefetch next iteration's point (1 wavefront, lanes 0..2) ----
        const int tid_n = tid + stride;
        float nv = 0.0f;
        if (tid_n < total) {                        // warp-uniform
            const int bn = tid_n >> 5;
            if (lane < 3) nv = __ldcg(x + 3 * bn + lane);
        }

        const int b = tid >> 5;

        // xp = (x + 1) * (res/2) - 0.5, exact f32 op order of the reference.
        const float xp = __fadd_rn(__fmul_rn(__fadd_rn(px, 1.0f), sc), -0.5f);
        const float yp = __fadd_rn(__fmul_rn(__fadd_rn(py, 1.0f), sc), -0.5f);
        const float zp = __fadd_rn(__fmul_rn(__fadd_rn(pz, 1.0f), sc), -0.5f);

        const float fx = floorf(xp), fy = floorf(yp), fz = floorf(zp);
        const int ix = (int)fx, iy = (int)fy, iz = (int)fz;
        const float tx = __fsub_rn(xp, fx);
        const float ty = __fsub_rn(yp, fy);
        const float tz = __fsub_rn(zp, fz);
        const float ux = __fsub_rn(1.0f, tx);
        const float uy = __fsub_rn(1.0f, ty);
        const float uz = __fsub_rn(1.0f, tz);

        // This lane's x-corner (shared by its 4 corners).
        const int   cx = ix + ox;
        const float wx = ox ? tx : ux;
        const bool  vx = ((unsigned)cx < (unsigned)res);

        // ---- 4 corners (oy,oz); paired lanes (ox=0/1) coalesce in L1TEX ----
        float    w[4];
        unsigned idx[4];
        #pragma unroll
        for (int cc = 0; cc < 4; ++cc) {
            const int oy = (cc >> 1) & 1, oz = cc & 1;
            const int cy = iy + oy, cz = iz + oz;
            const bool valid = vx & ((unsigned)cy < (unsigned)res)
                                  & ((unsigned)cz < (unsigned)res);
            const float ww = __fmul_rn(__fmul_rn(wx, oy ? ty : uy), oz ? tz : uz);
            w[cc] = valid ? ww : 0.0f;

            const unsigned hidx = ((unsigned)cx ^ ((unsigned)cy * P1)
                                                ^ ((unsigned)cz * P2)) & HMASK;
            const unsigned didx = (unsigned)(cx + cy * res + cz * res2);
            const unsigned ii = use_hash ? hidx : didx;
            idx[cc] = valid ? ii : 0u;
        }

        // ---- batched 4-wide gather: smem (l<2) or L2-only global (l>=2) ----
        float2 e[4];
        if (in_smem) {
            #pragma unroll
            for (int cc = 0; cc < 4; ++cc) e[cc] = stab[idx[cc]];
        } else {
            #pragma unroll
            for (int cc = 0; cc < 4; ++cc) e[cc] = __ldcg(&gtab[idx[cc]]);
        }

        float a0 = 0.0f, a1 = 0.0f;
        #pragma unroll
        for (int cc = 0; cc < 4; ++cc) {
            a0 = fmaf(e[cc].x, w[cc], a0);
            a1 = fmaf(e[cc].y, w[cc], a1);
        }

        // Pair reduction: even lane accumulates the odd lane's 4 corners.
        a0 += __shfl_xor_sync(FULL, a0, 1);
        a1 += __shfl_xor_sync(FULL, a1, 1);

        if (ox == 0) {
            // 16 even lanes store 128 contiguous bytes per warp.
            __stcs(&out[(size_t)b * NLEVELS + l], make_float2(a0, a1));
        }

        if (tid_n >= total) break;
        tid = tid_n;
        px = __shfl_sync(FULL, nv, 0);
        py = __shfl_sync(FULL, nv, 1);
        pz = __shfl_sync(FULL, nv, 2);
    }
}

extern "C" void kernel_launch(void* const* d_in, const int* in_sizes, int n_in,
                              void* d_out, int out_size)
{
    const float* x = (const float*)d_in[0];
    Params p;
    #pragma unroll
    for (int l = 0; l < NLEVELS; ++l) {
        p.tab[l] = (const float2*)d_in[1 + l];
    }
    const int B = in_sizes[0] / 3;

    cudaFuncSetAttribute(hashenc_kernel,
                         cudaFuncAttributeMaxDynamicSharedMemorySize, SMEM_BYTES);

    int sms = 148;
    cudaDeviceGetAttribute(&sms, cudaDevAttrMultiProcessorCount, 0);

    hashenc_kernel<<<2 * sms, TPB, SMEM_BYTES>>>(x, p, (float2*)d_out, B);
}

// round 17
// speedup vs baseline: 1.0098x; 1.0098x over previous
#include <cuda_runtime.h>
#include <stdint.h>

// MultiLevelHybridHashEncoding — instant-NGP hash-grid encoding. FINAL (R15).
// 644us (naive) -> 242.8us across 15 rounds. Winning structure:
//  - 32 lanes = 1 point; lane pair = (level, x-half). The two x-adjacent
//    corners land on adjacent lanes so their table entries (idx/idx+1 dense,
//    idx/idx^1 hash) coalesce into one 128B line per pair in L1TEX -> cuts
//    gather line-wavefronts ~35% (the dominant, structural win).
//  - levels 0..1 staged in shared memory (96.8KB/CTA, 2 CTAs x 832 thr/SM =
//    52 warps; feed measured saturated at 52).
//  - levels >=2 gathered with __ldcg (L2-only, no L1 allocation) and x loaded
//    via one lane-distributed LDG + shfl broadcast; output via __stcs --
//    keeps DRAM at compulsory traffic and L1D unpolluted.
//  - persistent grid + next-point prefetch; shfl pair-reduce; 16 even lanes
//    store 128 contiguous bytes per warp.
// Profile at plateau: L1TEX 84.6% busy at the ~60 line-wavefront/point floor;
// occupancy/MLP/scheduling levers all measured neutral-or-negative.

#define NLEVELS 16
#define TPB 832

#define L0_N 4096    // 16^3
#define L1_N 8000    // 20^3
#define SMEM_BYTES ((L0_N + L1_N) * 8)   // 96768 B per CTA

#define P1 2654435761u
#define P2 805459861u
#define HMASK 0x7FFFFu
#define FULL 0xffffffffu

struct Params {
    const float2* tab[NLEVELS];
};

__device__ __constant__ int c_res[NLEVELS] = {
    16, 20, 25, 32, 40, 50, 64, 80, 101, 128, 161, 203, 256, 322, 406, 512
};

extern __shared__ float2 s_tab[];

__global__ void __launch_bounds__(TPB, 2)
hashenc_kernel(const float* __restrict__ x, Params p,
               float2* __restrict__ out, int B)
{
    // ---- cooperative smem fill: levels 0..1, coalesced ----
    {
        const float2* __restrict__ t0 = p.tab[0];
        const float2* __restrict__ t1 = p.tab[1];
        for (int i = threadIdx.x; i < L0_N; i += TPB) s_tab[i] = __ldg(t0 + i);
        for (int i = threadIdx.x; i < L1_N; i += TPB) s_tab[L0_N + i] = __ldg(t1 + i);
    }
    __syncthreads();

    // Thread = (point, level, x-half). 32 consecutive threads = 1 point.
    const int   lane     = threadIdx.x & 31;
    const int   ox       = threadIdx.x & 1;        // x-corner this lane owns
    const int   l        = (threadIdx.x >> 1) & 15;
    const int   res      = c_res[l];
    const int   res2     = res * res;
    const float sc       = 0.5f * (float)res;
    const bool  in_smem  = (l < 2);
    const bool  use_hash = (l >= 8);
    const float2* __restrict__ gtab = p.tab[l];
    const float2* __restrict__ stab = s_tab + (l == 0 ? 0 : L0_N);

    const int total  = B * NLEVELS * 2;             // (point, level, half) items
    const int stride = gridDim.x * TPB;
    int tid = blockIdx.x * TPB + threadIdx.x;
    if (tid >= total) return;

    // Prologue: lanes 0..2 fetch the 12B point; broadcast via shfl.
    float xv = 0.0f;
    {
        const int b = tid >> 5;
        if (lane < 3) xv = __ldcg(x + 3 * b + lane);
    }
    float px = __shfl_sync(FULL, xv, 0);
    float py = __shfl_sync(FULL, xv, 1);
    float pz = __shfl_sync(FULL, xv, 2);

    while (true) {
        // ---- prefetch next iteration's point (1 wavefront, lanes 0..2) ----
        const int tid_n = tid + stride;
        float nv = 0.0f;
        if (tid_n < total) {                        // warp-uniform
            const int bn = tid_n >> 5;
            if (lane < 3) nv = __ldcg(x + 3 * bn + lane);
        }

        const int b = tid >> 5;

        // xp = (x + 1) * (res/2) - 0.5, exact f32 op order of the reference.
        const float xp = __fadd_rn(__fmul_rn(__fadd_rn(px, 1.0f), sc), -0.5f);
        const float yp = __fadd_rn(__fmul_rn(__fadd_rn(py, 1.0f), sc), -0.5f);
        const float zp = __fadd_rn(__fmul_rn(__fadd_rn(pz, 1.0f), sc), -0.5f);

        const float fx = floorf(xp), fy = floorf(yp), fz = floorf(zp);
        const int ix = (int)fx, iy = (int)fy, iz = (int)fz;
        const float tx = __fsub_rn(xp, fx);
        const float ty = __fsub_rn(yp, fy);
        const float tz = __fsub_rn(zp, fz);
        const float ux = __fsub_rn(1.0f, tx);
        const float uy = __fsub_rn(1.0f, ty);
        const float uz = __fsub_rn(1.0f, tz);

        // This lane's x-corner (shared by its 4 corners).
        const int   cx = ix + ox;
        const float wx = ox ? tx : ux;
        const bool  vx = ((unsigned)cx < (unsigned)res);

        // ---- 4 corners (oy,oz); paired lanes (ox=0/1) coalesce in L1TEX ----
        float    w[4];
        unsigned idx[4];
        #pragma unroll
        for (int cc = 0; cc < 4; ++cc) {
            const int oy = (cc >> 1) & 1, oz = cc & 1;
            const int cy = iy + oy, cz = iz + oz;
            const bool valid = vx & ((unsigned)cy < (unsigned)res)
                                  & ((unsigned)cz < (unsigned)res);
            const float ww = __fmul_rn(__fmul_rn(wx, oy ? ty : uy), oz ? tz : uz);
            w[cc] = valid ? ww : 0.0f;

            const unsigned hidx = ((unsigned)cx ^ ((unsigned)cy * P1)
                                                ^ ((unsigned)cz * P2)) & HMASK;
            const unsigned didx = (unsigned)(cx + cy * res + cz * res2);
            const unsigned ii = use_hash ? hidx : didx;
            idx[cc] = valid ? ii : 0u;
        }

        // ---- batched 4-wide gather: smem (l<2) or L2-only global (l>=2) ----
        float2 e[4];
        if (in_smem) {
            #pragma unroll
            for (int cc = 0; cc < 4; ++cc) e[cc] = stab[idx[cc]];
        } else {
            #pragma unroll
            for (int cc = 0; cc < 4; ++cc) e[cc] = __ldcg(&gtab[idx[cc]]);
        }

        float a0 = 0.0f, a1 = 0.0f;
        #pragma unroll
        for (int cc = 0; cc < 4; ++cc) {
            a0 = fmaf(e[cc].x, w[cc], a0);
            a1 = fmaf(e[cc].y, w[cc], a1);
        }

        // Pair reduction: even lane accumulates the odd lane's 4 corners.
        a0 += __shfl_xor_sync(FULL, a0, 1);
        a1 += __shfl_xor_sync(FULL, a1, 1);

        if (ox == 0) {
            // 16 even lanes store 128 contiguous bytes per warp.
            __stcs(&out[(size_t)b * NLEVELS + l], make_float2(a0, a1));
        }

        if (tid_n >= total) break;
        tid = tid_n;
        px = __shfl_sync(FULL, nv, 0);
        py = __shfl_sync(FULL, nv, 1);
        pz = __shfl_sync(FULL, nv, 2);
    }
}

extern "C" void kernel_launch(void* const* d_in, const int* in_sizes, int n_in,
                              void* d_out, int out_size)
{
    const float* x = (const float*)d_in[0];
    Params p;
    #pragma unroll
    for (int l = 0; l < NLEVELS; ++l) {
        p.tab[l] = (const float2*)d_in[1 + l];
    }
    const int B = in_sizes[0] / 3;

    cudaFuncSetAttribute(hashenc_kernel,
                         cudaFuncAttributeMaxDynamicSharedMemorySize, SMEM_BYTES);

    int sms = 148;
    cudaDeviceGetAttribute(&sms, cudaDevAttrMultiProcessorCount, 0);

    hashenc_kernel<<<2 * sms, TPB, SMEM_BYTES>>>(x, p, (float2*)d_out, B);
}